// round 3
// baseline (speedup 1.0000x reference)
#include <cuda_runtime.h>
#include <math.h>

#define NN 50000
#define EE 800000
#define GG 512

// ---------------- device scratch (no allocations allowed) ----------------
__device__ float g_wcat[256 * 576];                 // concatenated weights [K, Npad]
__device__ float g_hcat[(size_t)NN * 576];          // [h | res | asrc | adst] per node
__device__ float g_agg[(size_t)NN * 256];           // aggregated GAT output
__device__ float g_xA[(size_t)NN * 256];            // h1
__device__ float g_xB[(size_t)NN * 128];            // h2
__device__ float g_xC[(size_t)NN * 128];            // h3
__device__ float g_denom[(size_t)NN * 8];           // softmax denominators
__device__ int   g_cnt[GG];

// ---------------- build concatenated weight matrix ----------------
// Columns: [0,D) = W, [D,2D) = pw, [2D,2D+H) = W @ a_src^T, [2D+H,2D+2H) = W @ a_dst^T, rest 0
__global__ void build_wcat(const float* __restrict__ W, const float* __restrict__ pw,
                           const float* __restrict__ as, const float* __restrict__ ad,
                           int K, int D, int H, int ch, int Npad) {
    int idx = blockIdx.x * blockDim.x + threadIdx.x;
    if (idx >= K * Npad) return;
    int k = idx / Npad, j = idx % Npad;
    float v = 0.f;
    if (j < D) {
        v = W[k * D + j];
    } else if (j < 2 * D) {
        v = pw[k * D + (j - D)];
    } else if (j < 2 * D + H) {
        int h = j - 2 * D; float s = 0.f;
        for (int c = 0; c < ch; c++) s += W[k * D + h * ch + c] * as[h * ch + c];
        v = s;
    } else if (j < 2 * D + 2 * H) {
        int h = j - 2 * D - H; float s = 0.f;
        for (int c = 0; c < ch; c++) s += W[k * D + h * ch + c] * ad[h * ch + c];
        v = s;
    }
    g_wcat[k * Npad + j] = v;
}

// ---------------- tiled fp32 GEMM: C[M,N] = A[M,K] @ B[K,N] ----------------
// BM=BN=64, BK=16, 256 threads, 4x4 per-thread microtile. N multiple of 64, K multiple of 16.
__global__ void gemm64(const float* __restrict__ A, const float* __restrict__ B,
                       float* __restrict__ C, int M, int N, int K) {
    __shared__ float As[16][64];
    __shared__ float Bs[16][64];
    int tid = threadIdx.x;
    int tx = tid & 15, ty = tid >> 4;
    int bm = blockIdx.y * 64, bn = blockIdx.x * 64;
    float acc[4][4] = {};

    int arow = tid >> 2;       // 0..63
    int akq  = tid & 3;        // which float4 along K
    int brow = tid >> 4;       // 0..15 (k)
    int bcq  = tid & 15;       // float4 along N

    for (int k0 = 0; k0 < K; k0 += 16) {
        float4 av = make_float4(0.f, 0.f, 0.f, 0.f);
        int gr = bm + arow;
        if (gr < M) av = *(const float4*)&A[(size_t)gr * K + k0 + akq * 4];
        As[akq * 4 + 0][arow] = av.x;
        As[akq * 4 + 1][arow] = av.y;
        As[akq * 4 + 2][arow] = av.z;
        As[akq * 4 + 3][arow] = av.w;
        *(float4*)&Bs[brow][bcq * 4] =
            *(const float4*)&B[(size_t)(k0 + brow) * N + bn + bcq * 4];
        __syncthreads();
#pragma unroll
        for (int kk = 0; kk < 16; kk++) {
            float4 a = *(float4*)&As[kk][ty * 4];
            float4 b = *(float4*)&Bs[kk][tx * 4];
            float ar[4] = {a.x, a.y, a.z, a.w};
            float br[4] = {b.x, b.y, b.z, b.w};
#pragma unroll
            for (int i = 0; i < 4; i++)
#pragma unroll
                for (int j = 0; j < 4; j++) acc[i][j] += ar[i] * br[j];
        }
        __syncthreads();
    }
#pragma unroll
    for (int i = 0; i < 4; i++) {
        int r = bm + ty * 4 + i;
        if (r < M) {
            float4 o = make_float4(acc[i][0], acc[i][1], acc[i][2], acc[i][3]);
            *(float4*)&C[(size_t)r * N + bn + tx * 4] = o;
        }
    }
}

__device__ __forceinline__ float lrelu02(float t) { return t > 0.f ? t : 0.2f * t; }

// ---------------- softmax denominator: self-loop init ----------------
__global__ void denom_self(int stride, int offAs, int offAd, int H) {
    int idx = blockIdx.x * blockDim.x + threadIdx.x;
    if (idx >= NN * H) return;
    int n = idx / H, h = idx - n * H;
    const float* row = &g_hcat[(size_t)n * stride];
    float t = lrelu02(row[offAs + h] + row[offAd + h]);
    g_denom[n * H + h] = __expf(t);
}

// ---------------- softmax denominator: edge accumulation ----------------
__global__ void denom_edge(const int* __restrict__ ei, int stride, int offAs, int offAd, int H) {
    int e = blockIdx.x * blockDim.x + threadIdx.x;
    if (e >= EE) return;
    int s = __ldg(&ei[e]);
    int d = __ldg(&ei[EE + e]);
    const float* rs = &g_hcat[(size_t)s * stride + offAs];
    const float* rd = &g_hcat[(size_t)d * stride + offAd];
    float p[8];
#pragma unroll 8
    for (int h = 0; h < H; h++) {
        if (h < H) p[h] = __expf(lrelu02(rs[h] + rd[h]));
    }
    float* db = &g_denom[(size_t)d * H];
    if (H == 8) {
        atomicAdd((float4*)db,       make_float4(p[0], p[1], p[2], p[3]));
        atomicAdd((float4*)(db + 4), make_float4(p[4], p[5], p[6], p[7]));
    } else if (H == 4) {
        atomicAdd((float4*)db, make_float4(p[0], p[1], p[2], p[3]));
    } else {
        atomicAdd(db, p[0]);
    }
}

// ---------------- initialize agg with self-loop message (non-atomic) ----------------
__global__ void self_out(int stride, int offAs, int offAd, int H, int chLog2, int D) {
    int n = blockIdx.x * (blockDim.x >> 5) + (threadIdx.x >> 5);
    if (n >= NN) return;
    int lane = threadIdx.x & 31;
    const float* row = &g_hcat[(size_t)n * stride];
    for (int c = lane * 4; c < D; c += 128) {
        int h = c >> chLog2;
        float t = lrelu02(row[offAs + h] + row[offAd + h]);
        float alpha = __expf(t) / (g_denom[n * H + h] + 1e-16f);
        float4 v = *(const float4*)&row[c];
        *(float4*)&g_agg[(size_t)n * D + c] =
            make_float4(v.x * alpha, v.y * alpha, v.z * alpha, v.w * alpha);
    }
}

// ---------------- edge scatter: agg[dst] += alpha * h[src] ----------------
__global__ void edge_scatter(const int* __restrict__ ei, int stride, int offAs, int offAd,
                             int H, int chLog2, int D) {
    int e = blockIdx.x * (blockDim.x >> 5) + (threadIdx.x >> 5);
    if (e >= EE) return;
    int lane = threadIdx.x & 31;
    int s = __ldg(&ei[e]);
    int d = __ldg(&ei[EE + e]);
    const float* rs = &g_hcat[(size_t)s * stride];
    const float* rd = &g_hcat[(size_t)d * stride];
    for (int c = lane * 4; c < D; c += 128) {
        int h = c >> chLog2;
        float t = lrelu02(rs[offAs + h] + rd[offAd + h]);
        float alpha = __expf(t) / (g_denom[(size_t)d * H + h] + 1e-16f);
        float4 v = *(const float4*)&rs[c];
        atomicAdd((float4*)&g_agg[(size_t)d * D + c],
                  make_float4(v.x * alpha, v.y * alpha, v.z * alpha, v.w * alpha));
    }
}

// ---------------- combine: elu( LN(agg + b)*g+be + res + pb ) ----------------
__global__ void combine(const float* __restrict__ b, const float* __restrict__ gam,
                        const float* __restrict__ bet, const float* __restrict__ pb,
                        float* __restrict__ xout, int stride, int offRes, int D) {
    int n = blockIdx.x * (blockDim.x >> 5) + (threadIdx.x >> 5);
    if (n >= NN) return;
    int lane = threadIdx.x & 31;
    const float* row = &g_hcat[(size_t)n * stride];
    int nk = D >> 7;  // float4 iterations per lane (D=128 -> 1, D=256 -> 2)
    float4 vals[2];
    float sum = 0.f, sum2 = 0.f;
    for (int it = 0; it < nk; it++) {
        int c = it * 128 + lane * 4;
        float4 a = *(float4*)&g_agg[(size_t)n * D + c];
        float4 bb = *(const float4*)&b[c];
        a.x += bb.x; a.y += bb.y; a.z += bb.z; a.w += bb.w;
        vals[it] = a;
        sum  += a.x + a.y + a.z + a.w;
        sum2 += a.x * a.x + a.y * a.y + a.z * a.z + a.w * a.w;
    }
#pragma unroll
    for (int o = 16; o; o >>= 1) {
        sum  += __shfl_xor_sync(0xffffffffu, sum, o);
        sum2 += __shfl_xor_sync(0xffffffffu, sum2, o);
    }
    float invD = 1.f / (float)D;
    float mean = sum * invD;
    float var = sum2 * invD - mean * mean;
    float inv = rsqrtf(var + 1e-5f);
    for (int it = 0; it < nk; it++) {
        int c = it * 128 + lane * 4;
        float4 a = vals[it];
        float4 gg = *(const float4*)&gam[c];
        float4 be4 = *(const float4*)&bet[c];
        float4 rr = *(const float4*)&row[offRes + c];
        float4 pp = *(const float4*)&pb[c];
        float y0 = (a.x - mean) * inv * gg.x + be4.x + rr.x + pp.x;
        float y1 = (a.y - mean) * inv * gg.y + be4.y + rr.y + pp.y;
        float y2 = (a.z - mean) * inv * gg.z + be4.z + rr.z + pp.z;
        float y3 = (a.w - mean) * inv * gg.w + be4.w + rr.w + pp.w;
        y0 = y0 > 0.f ? y0 : expm1f(y0);
        y1 = y1 > 0.f ? y1 : expm1f(y1);
        y2 = y2 > 0.f ? y2 : expm1f(y2);
        y3 = y3 > 0.f ? y3 : expm1f(y3);
        *(float4*)&xout[(size_t)n * D + c] = make_float4(y0, y1, y2, y3);
    }
}

// ---------------- pooling ----------------
__global__ void pool_zero(float* __restrict__ out) {
    int idx = blockIdx.x * blockDim.x + threadIdx.x;
    if (idx < GG * 128) out[idx] = 0.f;
    if (idx < GG) g_cnt[idx] = 0;
}

__global__ void pool_acc(const float* __restrict__ x3, const int* __restrict__ batch,
                         float* __restrict__ out) {
    int n = blockIdx.x * (blockDim.x >> 5) + (threadIdx.x >> 5);
    if (n >= NN) return;
    int lane = threadIdx.x & 31;
    int g = __ldg(&batch[n]);
    int c = lane * 4;
    float4 v = *(const float4*)&x3[(size_t)n * 128 + c];
    atomicAdd((float4*)&out[(size_t)g * 128 + c], v);
    if (lane == 0) atomicAdd(&g_cnt[g], 1);
}

__global__ void pool_div(float* __restrict__ out) {
    int idx = blockIdx.x * blockDim.x + threadIdx.x;
    if (idx >= GG * 128) return;
    int g = idx >> 7;
    float c = (float)(g_cnt[g] > 0 ? g_cnt[g] : 1);
    out[idx] /= c;
}

// ---------------- host-side orchestration ----------------
struct LayerCfg {
    int K, D, H, ch, chLog2, Npad, offRes, offAs, offAd;
};

static void run_layer(const float* A,                   // input features [NN, K]
                      const float* W, const float* as, const float* ad,
                      const float* b, const float* gam, const float* bet,
                      const float* pw, const float* pb,
                      const int* ei, float* xout, const LayerCfg& L) {
    // 1. build concatenated weights
    {
        int total = L.K * L.Npad;
        build_wcat<<<(total + 255) / 256, 256>>>(W, pw, as, ad, L.K, L.D, L.H, L.ch, L.Npad);
    }
    // 2. fused GEMM: g_hcat = A @ wcat
    {
        dim3 grid(L.Npad / 64, (NN + 63) / 64);
        float* hcat;
        cudaGetSymbolAddress((void**)&hcat, g_hcat);
        float* wcat;
        cudaGetSymbolAddress((void**)&wcat, g_wcat);
        gemm64<<<grid, 256>>>(A, wcat, hcat, NN, L.Npad, L.K);
    }
    // 3. softmax denominators
    denom_self<<<(NN * L.H + 255) / 256, 256>>>(L.Npad, L.offAs, L.offAd, L.H);
    denom_edge<<<(EE + 255) / 256, 256>>>(ei, L.Npad, L.offAs, L.offAd, L.H);
    // 4. aggregate messages
    self_out<<<(NN + 7) / 8, 256>>>(L.Npad, L.offAs, L.offAd, L.H, L.chLog2, L.D);
    edge_scatter<<<(EE + 7) / 8, 256>>>(ei, L.Npad, L.offAs, L.offAd, L.H, L.chLog2, L.D);
    // 5. combine (bias + LN + residual + ELU)
    combine<<<(NN + 7) / 8, 256>>>(b, gam, bet, pb, xout, L.Npad, L.offRes, L.D);
}

extern "C" void kernel_launch(void* const* d_in, const int* in_sizes, int n_in,
                              void* d_out, int out_size) {
    const float* x    = (const float*)d_in[0];
    const int* ei     = (const int*)d_in[1];
    const int* batch  = (const int*)d_in[2];
    const float* W1 = (const float*)d_in[3],  *as1 = (const float*)d_in[4],
               *ad1 = (const float*)d_in[5],  *b1  = (const float*)d_in[6],
               *g1  = (const float*)d_in[7],  *be1 = (const float*)d_in[8],
               *pw1 = (const float*)d_in[9],  *pb1 = (const float*)d_in[10];
    const float* W2 = (const float*)d_in[11], *as2 = (const float*)d_in[12],
               *ad2 = (const float*)d_in[13], *b2  = (const float*)d_in[14],
               *g2  = (const float*)d_in[15], *be2 = (const float*)d_in[16],
               *pw2 = (const float*)d_in[17], *pb2 = (const float*)d_in[18];
    const float* W3 = (const float*)d_in[19], *as3 = (const float*)d_in[20],
               *ad3 = (const float*)d_in[21], *b3  = (const float*)d_in[22],
               *g3  = (const float*)d_in[23], *be3 = (const float*)d_in[24],
               *pw3 = (const float*)d_in[25], *pb3 = (const float*)d_in[26];
    float* out = (float*)d_out;

    float *xA, *xB, *xC;
    cudaGetSymbolAddress((void**)&xA, g_xA);
    cudaGetSymbolAddress((void**)&xB, g_xB);
    cudaGetSymbolAddress((void**)&xC, g_xC);

    // Layer 1: 128 -> 8 heads x 32 (concat -> 256)
    LayerCfg L1 = {128, 256, 8, 32, 5, 576, 256, 512, 520};
    run_layer(x, W1, as1, ad1, b1, g1, be1, pw1, pb1, ei, xA, L1);

    // Layer 2: 256 -> 4 heads x 32 (concat -> 128)
    LayerCfg L2 = {256, 128, 4, 32, 5, 320, 128, 256, 260};
    run_layer(xA, W2, as2, ad2, b2, g2, be2, pw2, pb2, ei, xB, L2);

    // Layer 3: 128 -> 1 head x 128 (mean over 1 head -> 128)
    LayerCfg L3 = {128, 128, 1, 128, 7, 320, 128, 256, 257};
    run_layer(xB, W3, as3, ad3, b3, g3, be3, pw3, pb3, ei, xC, L3);

    // Global mean pool per graph
    pool_zero<<<(GG * 128 + 255) / 256, 256>>>(out);
    pool_acc<<<(NN + 7) / 8, 256>>>(xC, batch, out);
    pool_div<<<(GG * 128 + 255) / 256, 256>>>(out);
}

// round 7
// speedup vs baseline: 1.6501x; 1.6501x over previous
#include <cuda_runtime.h>
#include <math.h>

#define NN 50000
#define EE 800000
#define GG 512
#define FULL 0xffffffffu

// ---------------- device scratch ----------------
__device__ float g_wcat[256 * 576];
__device__ float g_hcat[(size_t)NN * 576];
__device__ float g_xA[(size_t)NN * 256];
__device__ float g_xB[(size_t)NN * 128];
__device__ int   g_deg[NN];
__device__ int   g_rowptr[NN + 1];
__device__ int   g_cursor[NN];
__device__ int   g_csr[EE];
__device__ int   g_bsum[128];
__device__ int   g_cnt[GG];

__device__ __forceinline__ float lrelu02(float t) { return t > 0.f ? t : 0.2f * t; }

// ================= CSR build =================
__global__ void init_zero(float* __restrict__ out) {
    int i = blockIdx.x * blockDim.x + threadIdx.x;
    if (i < NN) g_deg[i] = 0;
    if (i < GG * 128) out[i] = 0.f;
    if (i < GG) g_cnt[i] = 0;
}

__global__ void count_deg(const int* __restrict__ ei) {
    int e = blockIdx.x * blockDim.x + threadIdx.x;
    if (e < EE) atomicAdd(&g_deg[ei[EE + e]], 1);
}

__global__ void scan1() {
    __shared__ int sh[512];
    int t = threadIdx.x;
    int i = blockIdx.x * 512 + t;
    int v = (i < NN) ? g_deg[i] : 0;
    sh[t] = v;
    __syncthreads();
    for (int off = 1; off < 512; off <<= 1) {
        int x = (t >= off) ? sh[t - off] : 0;
        __syncthreads();
        sh[t] += x;
        __syncthreads();
    }
    if (i < NN) g_rowptr[i] = sh[t] - v;     // block-local exclusive
    if (t == 511) g_bsum[blockIdx.x] = sh[t];
}

__global__ void scan2(int nb) {
    __shared__ int sh[128];
    int t = threadIdx.x;
    int v = (t < nb) ? g_bsum[t] : 0;
    sh[t] = v;
    __syncthreads();
    for (int off = 1; off < 128; off <<= 1) {
        int x = (t >= off) ? sh[t - off] : 0;
        __syncthreads();
        sh[t] += x;
        __syncthreads();
    }
    if (t < nb) g_bsum[t] = sh[t] - v;       // exclusive block offsets
    if (t == 0) g_rowptr[NN] = EE;
}

__global__ void scan3() {
    int i = blockIdx.x * blockDim.x + threadIdx.x;
    if (i >= NN) return;
    int r = g_rowptr[i] + g_bsum[i >> 9];
    g_rowptr[i] = r;
    g_cursor[i] = r;
}

__global__ void fill_csr(const int* __restrict__ ei) {
    int e = blockIdx.x * blockDim.x + threadIdx.x;
    if (e >= EE) return;
    int d = ei[EE + e];
    int pos = atomicAdd(&g_cursor[d], 1);
    g_csr[pos] = ei[e];
}

// ================= weight concat =================
// layout per row: [ W(0..D) | Wa_src(offAs..+H) | Wa_dst(offAd..+H) | pw(offRes..+D) | 0pad ]
__global__ void build_wcat(const float* __restrict__ W, const float* __restrict__ pw,
                           const float* __restrict__ as, const float* __restrict__ ad,
                           int K, int D, int H, int ch, int Npad,
                           int offAs, int offAd, int offRes) {
    int idx = blockIdx.x * blockDim.x + threadIdx.x;
    if (idx >= K * Npad) return;
    int k = idx / Npad, j = idx % Npad;
    float v = 0.f;
    if (j < D) {
        v = W[k * D + j];
    } else if (j >= offAs && j < offAs + H) {
        int h = j - offAs; float s = 0.f;
        for (int c = 0; c < ch; c++) s += W[k * D + h * ch + c] * as[h * ch + c];
        v = s;
    } else if (j >= offAd && j < offAd + H) {
        int h = j - offAd; float s = 0.f;
        for (int c = 0; c < ch; c++) s += W[k * D + h * ch + c] * ad[h * ch + c];
        v = s;
    } else if (j >= offRes && j < offRes + D) {
        v = pw[k * D + (j - offRes)];
    }
    g_wcat[k * Npad + j] = v;
}

// ================= f32x2 SGEMM =================
// C[M,N] = A[M,K] @ B[K,N].  BM=128, BN=64, BK=16, 128 threads, 8x8 microtile.
// Accumulators are f32x2 pairs along M (fma.rn.f32x2 -> 2x fp32 rate).
#define FMA2(c, a, b) asm("fma.rn.f32x2 %0, %1, %2, %0;" : "+l"(c) : "l"(a), "l"(b))
#define DUP2(d, s)    asm("mov.b64 %0, {%1, %1};" : "=l"(d) : "f"(s))

__global__ void __launch_bounds__(128)
gemm_f32x2(const float* __restrict__ A, const float* __restrict__ B,
           float* __restrict__ C, int M, int N, int K) {
    __shared__ float As[16][128];   // k-major, m contiguous
    __shared__ float Bs[16][64];
    int tid = threadIdx.x;
    int nx = tid & 7;               // 8 col groups of 8
    int my = tid >> 3;              // 16 row groups of 8
    int bm = blockIdx.y * 128, bn = blockIdx.x * 64;

    unsigned long long acc2[4][8];
#pragma unroll
    for (int p = 0; p < 4; p++)
#pragma unroll
        for (int j = 0; j < 8; j++) acc2[p][j] = 0ull;

    float4 ra[4], rb[2];
    // prefetch tile 0
#pragma unroll
    for (int i = 0; i < 4; i++) {
        int q = i * 128 + tid, ar = q >> 2, ac = q & 3;
        int row = bm + ar;
        ra[i] = (row < M) ? *(const float4*)&A[(size_t)row * K + ac * 4]
                          : make_float4(0.f, 0.f, 0.f, 0.f);
    }
#pragma unroll
    for (int i = 0; i < 2; i++) {
        int q = i * 128 + tid, br = q >> 4, bc = q & 15;
        rb[i] = *(const float4*)&B[(size_t)br * N + bn + bc * 4];
    }

    for (int k0 = 0; k0 < K; k0 += 16) {
        // commit prefetched tile to smem
#pragma unroll
        for (int i = 0; i < 4; i++) {
            int q = i * 128 + tid, ar = q >> 2, ac = q & 3;
            As[ac * 4 + 0][ar] = ra[i].x;
            As[ac * 4 + 1][ar] = ra[i].y;
            As[ac * 4 + 2][ar] = ra[i].z;
            As[ac * 4 + 3][ar] = ra[i].w;
        }
#pragma unroll
        for (int i = 0; i < 2; i++) {
            int q = i * 128 + tid, br = q >> 4, bc = q & 15;
            *(float4*)&Bs[br][bc * 4] = rb[i];
        }
        __syncthreads();
        // prefetch next tile
        if (k0 + 16 < K) {
#pragma unroll
            for (int i = 0; i < 4; i++) {
                int q = i * 128 + tid, ar = q >> 2, ac = q & 3;
                int row = bm + ar;
                ra[i] = (row < M) ? *(const float4*)&A[(size_t)row * K + k0 + 16 + ac * 4]
                                  : make_float4(0.f, 0.f, 0.f, 0.f);
            }
#pragma unroll
            for (int i = 0; i < 2; i++) {
                int q = i * 128 + tid, br = q >> 4, bc = q & 15;
                rb[i] = *(const float4*)&B[(size_t)(k0 + 16 + br) * N + bn + bc * 4];
            }
        }
#pragma unroll
        for (int kk = 0; kk < 16; kk++) {
            double2 da0 = *(const double2*)&As[kk][my * 8];
            double2 da1 = *(const double2*)&As[kk][my * 8 + 4];
            unsigned long long a2[4];
            a2[0] = __double_as_longlong(da0.x);
            a2[1] = __double_as_longlong(da0.y);
            a2[2] = __double_as_longlong(da1.x);
            a2[3] = __double_as_longlong(da1.y);
            float4 b0 = *(const float4*)&Bs[kk][nx * 8];
            float4 b1 = *(const float4*)&Bs[kk][nx * 8 + 4];
            unsigned long long bd[8];
            DUP2(bd[0], b0.x); DUP2(bd[1], b0.y); DUP2(bd[2], b0.z); DUP2(bd[3], b0.w);
            DUP2(bd[4], b1.x); DUP2(bd[5], b1.y); DUP2(bd[6], b1.z); DUP2(bd[7], b1.w);
#pragma unroll
            for (int j = 0; j < 8; j++)
#pragma unroll
                for (int p = 0; p < 4; p++)
                    FMA2(acc2[p][j], a2[p], bd[j]);
        }
        __syncthreads();
    }

    // epilogue
#pragma unroll
    for (int p = 0; p < 4; p++) {
        int r0 = bm + my * 8 + 2 * p;
        float2 f[8];
#pragma unroll
        for (int j = 0; j < 8; j++) {
            double d = __longlong_as_double(acc2[p][j]);
            f[j] = *(float2*)&d;
        }
        if (r0 < M) {
            *(float4*)&C[(size_t)r0 * N + bn + nx * 8]     = make_float4(f[0].x, f[1].x, f[2].x, f[3].x);
            *(float4*)&C[(size_t)r0 * N + bn + nx * 8 + 4] = make_float4(f[4].x, f[5].x, f[6].x, f[7].x);
        }
        if (r0 + 1 < M) {
            *(float4*)&C[(size_t)(r0 + 1) * N + bn + nx * 8]     = make_float4(f[0].y, f[1].y, f[2].y, f[3].y);
            *(float4*)&C[(size_t)(r0 + 1) * N + bn + nx * 8 + 4] = make_float4(f[4].y, f[5].y, f[6].y, f[7].y);
        }
    }
}

// ================= fused GAT aggregate + LN + residual + ELU =================
// one warp per destination node; CSR gather, unnormalized softmax, in-register LN.
template <int R4, int CHLOG2, bool POOL>
__global__ void __launch_bounds__(256)
gat_agg(int stride, int H, int offAs, int offAd, int offRes,
        const float* __restrict__ b, const float* __restrict__ gam,
        const float* __restrict__ bet, const float* __restrict__ pb,
        float* __restrict__ xout, const int* __restrict__ batch) {
    int n = blockIdx.x * 8 + (threadIdx.x >> 5);
    if (n >= NN) return;
    int lane = threadIdx.x & 31;
    const int D = R4 * 128;
    const float* row = &g_hcat[(size_t)n * stride];

    float adst_l = (lane < H) ? row[offAd + lane] : 0.f;

    // self-loop term
    float ps = 0.f;
    if (lane < H) ps = __expf(lrelu02(row[offAs + lane] + adst_l));
    float denom_l = ps;

    float4 acc[R4];
#pragma unroll
    for (int j = 0; j < R4; j++) {
        int c = 128 * j + 4 * lane;
        int h = c >> CHLOG2;
        float ph = __shfl_sync(FULL, ps, h);
        float4 v = *(const float4*)&row[c];
        acc[j] = make_float4(v.x * ph, v.y * ph, v.z * ph, v.w * ph);
    }

    int beg = g_rowptr[n], end = g_rowptr[n + 1];
    for (int base = beg; base < end; base += 32) {
        int m = min(32, end - base);
        int s_l = (base + lane < end) ? g_csr[base + lane] : 0;
        for (int t = 0; t < m; t++) {
            int s = __shfl_sync(FULL, s_l, t);
            const float* rs = &g_hcat[(size_t)s * stride];
            float pe = 0.f;
            if (lane < H) pe = __expf(lrelu02(rs[offAs + lane] + adst_l));
            denom_l += pe;
#pragma unroll
            for (int j = 0; j < R4; j++) {
                int c = 128 * j + 4 * lane;
                int h = c >> CHLOG2;
                float ph = __shfl_sync(FULL, pe, h);
                float4 v = *(const float4*)&rs[c];
                acc[j].x += ph * v.x; acc[j].y += ph * v.y;
                acc[j].z += ph * v.z; acc[j].w += ph * v.w;
            }
        }
    }

    // normalize, + bias, LN stats
    float sum = 0.f, sum2 = 0.f;
    float4 y[R4];
#pragma unroll
    for (int j = 0; j < R4; j++) {
        int c = 128 * j + 4 * lane;
        int h = c >> CHLOG2;
        float d = __shfl_sync(FULL, denom_l, h) + 1e-16f;
        float inv = 1.f / d;
        float4 bb = *(const float4*)&b[c];
        float4 a;
        a.x = acc[j].x * inv + bb.x;
        a.y = acc[j].y * inv + bb.y;
        a.z = acc[j].z * inv + bb.z;
        a.w = acc[j].w * inv + bb.w;
        y[j] = a;
        sum  += a.x + a.y + a.z + a.w;
        sum2 += a.x * a.x + a.y * a.y + a.z * a.z + a.w * a.w;
    }
#pragma unroll
    for (int o = 16; o; o >>= 1) {
        sum  += __shfl_xor_sync(FULL, sum, o);
        sum2 += __shfl_xor_sync(FULL, sum2, o);
    }
    float invD = 1.f / (float)D;
    float mean = sum * invD;
    float var = sum2 * invD - mean * mean;
    float rstd = rsqrtf(var + 1e-5f);

    int g = 0;
    if (POOL) g = __ldg(&batch[n]);
#pragma unroll
    for (int j = 0; j < R4; j++) {
        int c = 128 * j + 4 * lane;
        float4 gg = *(const float4*)&gam[c];
        float4 be4 = *(const float4*)&bet[c];
        float4 rr = *(const float4*)&row[offRes + c];
        float4 pp = *(const float4*)&pb[c];
        float y0 = (y[j].x - mean) * rstd * gg.x + be4.x + rr.x + pp.x;
        float y1 = (y[j].y - mean) * rstd * gg.y + be4.y + rr.y + pp.y;
        float y2 = (y[j].z - mean) * rstd * gg.z + be4.z + rr.z + pp.z;
        float y3 = (y[j].w - mean) * rstd * gg.w + be4.w + rr.w + pp.w;
        y0 = y0 > 0.f ? y0 : expm1f(y0);
        y1 = y1 > 0.f ? y1 : expm1f(y1);
        y2 = y2 > 0.f ? y2 : expm1f(y2);
        y3 = y3 > 0.f ? y3 : expm1f(y3);
        if (POOL) {
            atomicAdd((float4*)&xout[(size_t)g * 128 + c], make_float4(y0, y1, y2, y3));
        } else {
            *(float4*)&xout[(size_t)n * D + c] = make_float4(y0, y1, y2, y3);
        }
    }
    if (POOL && lane == 0) atomicAdd(&g_cnt[g], 1);
}

__global__ void pool_div(float* __restrict__ out) {
    int idx = blockIdx.x * blockDim.x + threadIdx.x;
    if (idx >= GG * 128) return;
    int g = idx >> 7;
    float c = (float)(g_cnt[g] > 0 ? g_cnt[g] : 1);
    out[idx] /= c;
}

// ================= host orchestration =================
extern "C" void kernel_launch(void* const* d_in, const int* in_sizes, int n_in,
                              void* d_out, int out_size) {
    const float* x    = (const float*)d_in[0];
    const int* ei     = (const int*)d_in[1];
    const int* batch  = (const int*)d_in[2];
    const float* W1 = (const float*)d_in[3],  *as1 = (const float*)d_in[4],
               *ad1 = (const float*)d_in[5],  *b1  = (const float*)d_in[6],
               *g1  = (const float*)d_in[7],  *be1 = (const float*)d_in[8],
               *pw1 = (const float*)d_in[9],  *pb1 = (const float*)d_in[10];
    const float* W2 = (const float*)d_in[11], *as2 = (const float*)d_in[12],
               *ad2 = (const float*)d_in[13], *b2  = (const float*)d_in[14],
               *g2  = (const float*)d_in[15], *be2 = (const float*)d_in[16],
               *pw2 = (const float*)d_in[17], *pb2 = (const float*)d_in[18];
    const float* W3 = (const float*)d_in[19], *as3 = (const float*)d_in[20],
               *ad3 = (const float*)d_in[21], *b3  = (const float*)d_in[22],
               *g3  = (const float*)d_in[23], *be3 = (const float*)d_in[24],
               *pw3 = (const float*)d_in[25], *pb3 = (const float*)d_in[26];
    float* out = (float*)d_out;

    float *hcat, *wcat, *xA, *xB;
    cudaGetSymbolAddress((void**)&hcat, g_hcat);
    cudaGetSymbolAddress((void**)&wcat, g_wcat);
    cudaGetSymbolAddress((void**)&xA, g_xA);
    cudaGetSymbolAddress((void**)&xB, g_xB);

    // --- CSR build (shared by all layers) + zero out/cnt ---
    init_zero<<<(GG * 128 + 255) / 256, 256>>>(out);
    count_deg<<<(EE + 255) / 256, 256>>>(ei);
    int nb = (NN + 511) / 512;
    scan1<<<nb, 512>>>();
    scan2<<<1, 128>>>(nb);
    scan3<<<(NN + 255) / 256, 256>>>();
    fill_csr<<<(EE + 255) / 256, 256>>>(ei);

    // --- Layer 1: 128 -> 8x32 (concat 256). layout: h 0-255, as 256-263, ad 264-271, res 272-527, pad->576
    build_wcat<<<(128 * 576 + 255) / 256, 256>>>(W1, pw1, as1, ad1, 128, 256, 8, 32, 576, 256, 264, 272);
    {
        dim3 grid(576 / 64, (NN + 127) / 128);
        gemm_f32x2<<<grid, 128>>>(x, wcat, hcat, NN, 576, 128);
    }
    gat_agg<2, 5, false><<<(NN + 7) / 8, 256>>>(576, 8, 256, 264, 272, b1, g1, be1, pb1, xA, nullptr);

    // --- Layer 2: 256 -> 4x32 (concat 128). h 0-127, as 128-131, ad 132-135, res 136-263, pad->320
    build_wcat<<<(256 * 320 + 255) / 256, 256>>>(W2, pw2, as2, ad2, 256, 128, 4, 32, 320, 128, 132, 136);
    {
        dim3 grid(320 / 64, (NN + 127) / 128);
        gemm_f32x2<<<grid, 128>>>(xA, wcat, hcat, NN, 320, 256);
    }
    gat_agg<1, 5, false><<<(NN + 7) / 8, 256>>>(320, 4, 128, 132, 136, b2, g2, be2, pb2, xB, nullptr);

    // --- Layer 3: 128 -> 1x128 (mean over 1 head). h 0-127, as 128, ad 129, res 132-259, pad->320
    build_wcat<<<(128 * 320 + 255) / 256, 256>>>(W3, pw3, as3, ad3, 128, 128, 1, 128, 320, 128, 129, 132);
    {
        dim3 grid(320 / 64, (NN + 127) / 128);
        gemm_f32x2<<<grid, 128>>>(xB, wcat, hcat, NN, 320, 128);
    }
    gat_agg<1, 7, true><<<(NN + 7) / 8, 256>>>(320, 1, 128, 129, 132, b3, g3, be3, pb3, out, batch);

    pool_div<<<(GG * 128 + 255) / 256, 256>>>(out);
}